// round 5
// baseline (speedup 1.0000x reference)
#include <cuda_runtime.h>
#include <math.h>

// Problem constants
//   x:     (1, 128, 32, 32, 32) fp32
//   w_qkv: (384, 128) fp32
//   subsample ::2 -> (128, 16,16,16), N = 4096 tokens
//   HEADS=4, head_dim=32, d_half=16, scale=1/sqrt(32), LAMBDA=0.1
//   out:   (1, 128, 16,16,16) fp32 ; flat index = h*131072 + n*32 + d

#define N_TOK   4096
#define LAMBDA_F 0.1f
#define NEG_INF (-1e30f)

// Scratch (device globals — no allocation)
__device__ float g_qkv[384 * 4096];        // q,k rows: [o][n], o = h*96 + r (r<64 used)
__device__ float g_vT[4 * 4096 * 32];      // v transposed: [h][n][d]

// ---------------------------------------------------------------------------
// Kernel 1: QKV projection with strided (::2) gather.
// qkv[o][n] = sum_c w[o][c] * xs[c][n]
// grid (64 n-tiles, 6 o-tiles), 256 threads, 64x64 output tile, K=128 in 2 steps.
// ---------------------------------------------------------------------------
__global__ __launch_bounds__(256) void qkv_proj_kernel(const float* __restrict__ x,
                                                       const float* __restrict__ w) {
    __shared__ float sW[64 * 64];   // [o_local][k_local]
    __shared__ float sX[64 * 64];   // [c_local][n_local]
    const int tid = threadIdx.x;
    const int n0 = blockIdx.x * 64;
    const int o0 = blockIdx.y * 64;
    const int tx = tid & 15;        // n group (4 cols)
    const int ty = tid >> 4;        // o group (4 rows)

    float acc[4][4] = {};

    for (int k0 = 0; k0 < 128; k0 += 64) {
        __syncthreads();
        // load W tile (coalesced float4)
        for (int i = tid; i < 64 * 16; i += 256) {
            int r = i >> 4, q4 = i & 15;
            *(float4*)&sW[r * 64 + q4 * 4] =
                *(const float4*)&w[(o0 + r) * 128 + k0 + q4 * 4];
        }
        // gather X tile (strided subsample)
        for (int i = tid; i < 64 * 64; i += 256) {
            int cl = i >> 6, j = i & 63;
            int n = n0 + j;
            int hh = n >> 8, ww = (n >> 4) & 15, zz = n & 15;
            sX[cl * 64 + j] = x[(k0 + cl) * 32768 + hh * 2048 + ww * 64 + zz * 2];
        }
        __syncthreads();

        #pragma unroll
        for (int k = 0; k < 64; k += 4) {
            float xk[4][4];
            #pragma unroll
            for (int kk = 0; kk < 4; kk++) {
                float4 xv = *(float4*)&sX[(k + kk) * 64 + 4 * tx];
                xk[kk][0] = xv.x; xk[kk][1] = xv.y; xk[kk][2] = xv.z; xk[kk][3] = xv.w;
            }
            #pragma unroll
            for (int i = 0; i < 4; i++) {
                float4 wv = *(float4*)&sW[(4 * ty + i) * 64 + k];
                float wk[4] = {wv.x, wv.y, wv.z, wv.w};
                #pragma unroll
                for (int kk = 0; kk < 4; kk++)
                    #pragma unroll
                    for (int j = 0; j < 4; j++)
                        acc[i][j] += wk[kk] * xk[kk][j];
            }
        }
    }

    // write out: q/k rows -> g_qkv [o][n]; v rows -> g_vT [h][n][d]
    #pragma unroll
    for (int i = 0; i < 4; i++) {
        int o = o0 + 4 * ty + i;
        int r = o % 96;
        if (r < 64) {
            *(float4*)&g_qkv[o * 4096 + n0 + 4 * tx] =
                make_float4(acc[i][0], acc[i][1], acc[i][2], acc[i][3]);
        } else {
            int h = o / 96, d = r - 64;
            int nb = n0 + 4 * tx;
            #pragma unroll
            for (int j = 0; j < 4; j++)
                g_vT[(h * 4096 + nb + j) * 32 + d] = acc[i][j];
        }
    }
}

// ---------------------------------------------------------------------------
// Kernel 2: dual-softmax flash attention.
// grid (64 row-tiles, 4 heads), 256 threads, M=64 query rows, 32-key tiles.
// Per row two online-softmax states (q1k1 and q2k2), shared V.
// ---------------------------------------------------------------------------
__device__ __forceinline__ void ld8(const float* p, float* s) {
    float4 a = *(const float4*)p;
    float4 b = *(const float4*)(p + 4);
    s[0] = a.x; s[1] = a.y; s[2] = a.z; s[3] = a.w;
    s[4] = b.x; s[5] = b.y; s[6] = b.z; s[7] = b.w;
}
__device__ __forceinline__ void st8(float* p, const float* s) {
    *(float4*)p       = make_float4(s[0], s[1], s[2], s[3]);
    *(float4*)(p + 4) = make_float4(s[4], s[5], s[6], s[7]);
}

__global__ __launch_bounds__(256) void diff_attn_kernel(float* __restrict__ out) {
    __shared__ float sQ[32 * 64];    // [d][row] (q, pre-scaled)
    __shared__ float sK[32 * 32];    // [d][key]
    __shared__ float sV[32 * 32];    // [key][d]
    __shared__ float sS1[64 * 36];   // scores/probs matrix 1 (pad 36)
    __shared__ float sS2[64 * 36];   // scores/probs matrix 2

    const int tid = threadIdx.x;
    const int h = blockIdx.y;
    const int i0 = blockIdx.x * 64;
    const float scale = 0.17677669529663687f;   // 1/sqrt(32)

    const float* qb = g_qkv + (h * 96) * 4096 + i0;
    const float* kb = g_qkv + (h * 96 + 32) * 4096;
    const float* vb = g_vT + h * 4096 * 32;

    // load Q tile (scale folded in)
    for (int i = tid; i < 2048; i += 256) {
        int d = i >> 6, r = i & 63;
        sQ[i] = qb[d * 4096 + r] * scale;
    }

    // phase-A mapping: 2 rows x 4 cols per thread over 64x32 scores
    const int tx8 = tid & 7;     // col group
    const int ty2 = tid >> 3;    // row group (0..31)
    // phase-S/B mapping: 4 threads per row
    const int row = tid >> 2;    // 0..63
    const int seg = tid & 3;     // owns dims seg*8 .. seg*8+7 and cols seg*8..

    float m1 = NEG_INF, m2 = NEG_INF, l1 = 0.f, l2 = 0.f;
    float o1[8] = {}, o2[8] = {};

    for (int j0 = 0; j0 < N_TOK; j0 += 32) {
        __syncthreads();   // protect smem from previous iteration's readers
        // load K tile (d-major) and V tile (n-major), both coalesced
        for (int i = tid; i < 1024; i += 256) {
            int d = i >> 5, j = i & 31;
            sK[i] = kb[d * 4096 + j0 + j];
        }
        for (int i = tid; i < 1024; i += 256)
            sV[i] = vb[j0 * 32 + i];
        __syncthreads();

        // -------- phase A: scores (both halves) --------
        float a1[2][4] = {}, a2[2][4] = {};
        #pragma unroll
        for (int d = 0; d < 16; d++) {
            float2 q = *(float2*)&sQ[d * 64 + 2 * ty2];
            float4 kv = *(float4*)&sK[d * 32 + 4 * tx8];
            float kk[4] = {kv.x, kv.y, kv.z, kv.w};
            float qq[2] = {q.x, q.y};
            #pragma unroll
            for (int i = 0; i < 2; i++)
                #pragma unroll
                for (int j = 0; j < 4; j++)
                    a1[i][j] += qq[i] * kk[j];
        }
        #pragma unroll
        for (int d = 16; d < 32; d++) {
            float2 q = *(float2*)&sQ[d * 64 + 2 * ty2];
            float4 kv = *(float4*)&sK[d * 32 + 4 * tx8];
            float kk[4] = {kv.x, kv.y, kv.z, kv.w};
            float qq[2] = {q.x, q.y};
            #pragma unroll
            for (int i = 0; i < 2; i++)
                #pragma unroll
                for (int j = 0; j < 4; j++)
                    a2[i][j] += qq[i] * kk[j];
        }
        #pragma unroll
        for (int i = 0; i < 2; i++) {
            *(float4*)&sS1[(2 * ty2 + i) * 36 + 4 * tx8] =
                make_float4(a1[i][0], a1[i][1], a1[i][2], a1[i][3]);
            *(float4*)&sS2[(2 * ty2 + i) * 36 + 4 * tx8] =
                make_float4(a2[i][0], a2[i][1], a2[i][2], a2[i][3]);
        }
        __syncthreads();

        // -------- phase S: online softmax update (both states) --------
        {
            float s1[8], s2[8];
            float* p1 = &sS1[row * 36 + seg * 8];
            float* p2 = &sS2[row * 36 + seg * 8];
            ld8(p1, s1);
            ld8(p2, s2);

            float mx1 = s1[0], mx2 = s2[0];
            #pragma unroll
            for (int k = 1; k < 8; k++) { mx1 = fmaxf(mx1, s1[k]); mx2 = fmaxf(mx2, s2[k]); }
            mx1 = fmaxf(mx1, __shfl_xor_sync(0xffffffffu, mx1, 1));
            mx1 = fmaxf(mx1, __shfl_xor_sync(0xffffffffu, mx1, 2));
            mx2 = fmaxf(mx2, __shfl_xor_sync(0xffffffffu, mx2, 1));
            mx2 = fmaxf(mx2, __shfl_xor_sync(0xffffffffu, mx2, 2));

            float mn1 = fmaxf(m1, mx1), mn2 = fmaxf(m2, mx2);
            float al1 = __expf(m1 - mn1), al2 = __expf(m2 - mn2);

            float sum1 = 0.f, sum2 = 0.f;
            #pragma unroll
            for (int k = 0; k < 8; k++) {
                s1[k] = __expf(s1[k] - mn1); sum1 += s1[k];
                s2[k] = __expf(s2[k] - mn2); sum2 += s2[k];
            }
            st8(p1, s1);
            st8(p2, s2);

            sum1 += __shfl_xor_sync(0xffffffffu, sum1, 1);
            sum1 += __shfl_xor_sync(0xffffffffu, sum1, 2);
            sum2 += __shfl_xor_sync(0xffffffffu, sum2, 1);
            sum2 += __shfl_xor_sync(0xffffffffu, sum2, 2);

            l1 = l1 * al1 + sum1; m1 = mn1;
            l2 = l2 * al2 + sum2; m2 = mn2;
            #pragma unroll
            for (int k = 0; k < 8; k++) { o1[k] *= al1; o2[k] *= al2; }
        }
        __syncwarp();   // probs for a row are produced by the same warp's 4 lanes

        // -------- phase B: P @ V (both states, shared V) --------
        {
            const float* pr1 = &sS1[row * 36];
            const float* pr2 = &sS2[row * 36];
            const int vo = seg * 8;
            #pragma unroll 8
            for (int j = 0; j < 32; j++) {
                float p1 = pr1[j];
                float p2 = pr2[j];
                float4 va  = *(float4*)&sV[j * 32 + vo];
                float4 vbq = *(float4*)&sV[j * 32 + vo + 4];
                float vv[8] = {va.x, va.y, va.z, va.w, vbq.x, vbq.y, vbq.z, vbq.w};
                #pragma unroll
                for (int k = 0; k < 8; k++) {
                    o1[k] += p1 * vv[k];
                    o2[k] += p2 * vv[k];
                }
            }
        }
    }

    // epilogue: out = o1/l1 - LAMBDA * o2/l2
    float inv1 = 1.f / l1;
    float inv2 = LAMBDA_F / l2;
    float r0[8];
    #pragma unroll
    for (int k = 0; k < 8; k++) r0[k] = o1[k] * inv1 - o2[k] * inv2;

    float* dst = out + h * (N_TOK * 32) + (i0 + row) * 32 + seg * 8;
    *(float4*)dst       = make_float4(r0[0], r0[1], r0[2], r0[3]);
    *(float4*)(dst + 4) = make_float4(r0[4], r0[5], r0[6], r0[7]);
}

// ---------------------------------------------------------------------------
extern "C" void kernel_launch(void* const* d_in, const int* in_sizes, int n_in,
                              void* d_out, int out_size) {
    const float* x = (const float*)d_in[0];       // (1,128,32,32,32)
    const float* w = (const float*)d_in[1];       // (384,128)
    float* out = (float*)d_out;                   // (1,128,16,16,16) fp32

    qkv_proj_kernel<<<dim3(64, 6), 256>>>(x, w);
    diff_attn_kernel<<<dim3(64, 4), 256>>>(out);
}